// round 17
// baseline (speedup 1.0000x reference)
#include <cuda_runtime.h>
#include <math.h>

#define BATCH 32
#define HEADS 32
#define DIM   128
#define KVLEN 1024
#define HID   4096
#define NQKV  12288
#define ROTD  64
#define QKV_SPLITS 16     // chunk 256
#define OPJ_SPLITS 64     // chunk 64
#define XPAD  36          // padded float row stride for xs transpose

__device__ float g_attn[BATCH * HID];                    // 0.5 MB
__device__ float g_part[32 * BATCH * NQKV];              // 50 MB

// ---------- packed f32x2 helpers (FFMA2) ----------
__device__ __forceinline__ unsigned long long pk2(float a, float b) {
    return ((unsigned long long)__float_as_uint(b) << 32) |
            (unsigned long long)__float_as_uint(a);
}
__device__ __forceinline__ void fma2(unsigned long long &d,
                                     unsigned long long a,
                                     unsigned long long b) {
    asm("fma.rn.f32x2 %0, %1, %2, %0;" : "+l"(d) : "l"(a), "l"(b));
}
__device__ __forceinline__ float lo2(unsigned long long v) {
    return __uint_as_float((unsigned)v);
}
__device__ __forceinline__ float hi2(unsigned long long v) {
    return __uint_as_float((unsigned)(v >> 32));
}

// one k-step: 16 FFMA2 against one W row (4 cols) and 8 x values (R11 form)
__device__ __forceinline__ void gemm_step(unsigned long long acc[16],
                                          const float* xr, float4 w4) {
    unsigned long long x01 = *(const unsigned long long*)(xr);
    unsigned long long x23 = *(const unsigned long long*)(xr + 2);
    unsigned long long x45 = *(const unsigned long long*)(xr + 4);
    unsigned long long x67 = *(const unsigned long long*)(xr + 6);
    unsigned long long w0 = pk2(w4.x, w4.x);
    unsigned long long w1 = pk2(w4.y, w4.y);
    unsigned long long w2 = pk2(w4.z, w4.z);
    unsigned long long w3 = pk2(w4.w, w4.w);
    fma2(acc[0],  x01, w0); fma2(acc[1],  x23, w0);
    fma2(acc[2],  x45, w0); fma2(acc[3],  x67, w0);
    fma2(acc[4],  x01, w1); fma2(acc[5],  x23, w1);
    fma2(acc[6],  x45, w1); fma2(acc[7],  x67, w1);
    fma2(acc[8],  x01, w2); fma2(acc[9],  x23, w2);
    fma2(acc[10], x45, w2); fma2(acc[11], x67, w2);
    fma2(acc[12], x01, w3); fma2(acc[13], x23, w3);
    fma2(acc[14], x45, w3); fma2(acc[15], x67, w3);
}

// ---------- split-K GEMM (R11 core, CHUNK templated) ----------
template <int CHUNK>
__global__ void __launch_bounds__(256, 2)
gemm_splitk(const float* __restrict__ X, const float* __restrict__ W,
            float* __restrict__ part, int N, int K) {
    __shared__ float xs[CHUNK * XPAD];
    const int tcol = threadIdx.x & 63;
    const int bg   = threadIdx.x >> 6;                 // 0..3
    const int j    = blockIdx.x * 256 + tcol * 4;
    const int k0   = blockIdx.y * CHUNK;
    constexpr int CSH = (CHUNK == 256) ? 8 : (CHUNK == 128) ? 7 : 6;

    for (int i = threadIdx.x; i < BATCH * CHUNK; i += 256) {
        int b  = i >> CSH;           // i / CHUNK
        int kk = i & (CHUNK - 1);
        xs[kk * XPAD + b] = X[b * K + k0 + kk];
    }

    const float* wp = W + (size_t)k0 * N + j;
    float4 wA[8], wB[8];
#pragma unroll
    for (int u = 0; u < 8; u++)
        wA[u] = __ldcs((const float4*)(wp + (size_t)u * N));

    __syncthreads();

    unsigned long long acc[16];
#pragma unroll
    for (int i = 0; i < 16; i++) acc[i] = 0ull;

    const float* xp = xs + bg * 8;

#pragma unroll
    for (int kk16 = 0; kk16 < CHUNK; kk16 += 16) {
#pragma unroll
        for (int u = 0; u < 8; u++)
            wB[u] = __ldcs((const float4*)(wp + (size_t)(kk16 + 8 + u) * N));
#pragma unroll
        for (int u = 0; u < 8; u++)
            gemm_step(acc, xp + (kk16 + u) * XPAD, wA[u]);
        int nk = (kk16 + 16 < CHUNK) ? kk16 + 16 : 0;
#pragma unroll
        for (int u = 0; u < 8; u++)
            wA[u] = __ldcs((const float4*)(wp + (size_t)(nk + u) * N));
#pragma unroll
        for (int u = 0; u < 8; u++)
            gemm_step(acc, xp + (kk16 + 8 + u) * XPAD, wB[u]);
    }

    float* pb = part + (size_t)blockIdx.y * BATCH * N + j;
#pragma unroll
    for (int p = 0; p < 4; p++) {
        int b0 = bg * 8 + 2 * p;
        float4 v0 = make_float4(lo2(acc[p]), lo2(acc[4 + p]),
                                lo2(acc[8 + p]), lo2(acc[12 + p]));
        float4 v1 = make_float4(hi2(acc[p]), hi2(acc[4 + p]),
                                hi2(acc[8 + p]), hi2(acc[12 + p]));
        *(float4*)(pb + (size_t)b0 * N)       = v0;
        *(float4*)(pb + (size_t)(b0 + 1) * N) = v1;
    }
}

// ---------- vectorized deterministic split-K reduction (o-proj) ----------
// one float4 per thread; 4 independent partial sums (fixed tree, deterministic)
__global__ void __launch_bounds__(256, 4)
reduce_splitk4(const float* __restrict__ part, float* __restrict__ out, int N) {
    int i = blockIdx.x * 256 + threadIdx.x;          // float4 index
    if (i >= BATCH * N / 4) return;
    const float4* p4 = (const float4*)part + i;
    const size_t stride4 = (size_t)BATCH * N / 4;

    float4 a0 = make_float4(0.f, 0.f, 0.f, 0.f);
    float4 a1 = a0, a2 = a0, a3 = a0;
#pragma unroll
    for (int g = 0; g < OPJ_SPLITS; g += 4) {
        float4 v0 = __ldcs(p4 + (size_t)(g + 0) * stride4);
        float4 v1 = __ldcs(p4 + (size_t)(g + 1) * stride4);
        float4 v2 = __ldcs(p4 + (size_t)(g + 2) * stride4);
        float4 v3 = __ldcs(p4 + (size_t)(g + 3) * stride4);
        a0.x += v0.x; a0.y += v0.y; a0.z += v0.z; a0.w += v0.w;
        a1.x += v1.x; a1.y += v1.y; a1.z += v1.z; a1.w += v1.w;
        a2.x += v2.x; a2.y += v2.y; a2.z += v2.z; a2.w += v2.w;
        a3.x += v3.x; a3.y += v3.y; a3.z += v3.z; a3.w += v3.w;
    }
    float4 r;
    r.x = (a0.x + a1.x) + (a2.x + a3.x);
    r.y = (a0.y + a1.y) + (a2.y + a3.y);
    r.z = (a0.z + a1.z) + (a2.z + a3.z);
    r.w = (a0.w + a1.w) + (a2.w + a3.w);
    ((float4*)out)[i] = r;
}

// ---------- attention with fused QKV split-reduce + RoPE prologue ----------
__global__ void __launch_bounds__(128)
attn_kernel(const float* __restrict__ part, const float* __restrict__ cache,
            const int* __restrict__ idx, const float* __restrict__ cosb,
            const float* __restrict__ sinb) {
    const int bh = blockIdx.x;
    const int b = bh >> 5, h = bh & 31;
    const int tid = threadIdx.x;
    const int warp = tid >> 5, lane = tid & 31;

    __shared__ float sc[KVLEN];
    __shared__ float red[4 * DIM];
    __shared__ float qs[DIM], ks[DIM], vs[DIM];
    __shared__ float wredA[4], wredB[4];

    const int p = idx[b] - b * KVLEN;
    const float scale = 0.08838834764831845f;   // 1/sqrt(128)

    // --- prologue: reduce q/k/v over splits (sp ascending) ---
    {
        const float* pp = part + (size_t)b * NQKV + h * DIM + tid;
        float sq = 0.f, sk = 0.f, sv = 0.f;
#pragma unroll
        for (int sp = 0; sp < QKV_SPLITS; sp++) {
            const float* base = pp + (size_t)sp * BATCH * NQKV;
            sq += __ldcs(base);
            sk += __ldcs(base + HID);
            sv += __ldcs(base + 2 * HID);
        }
        qs[tid] = sq; ks[tid] = sk; vs[tid] = sv;
    }
    __syncthreads();
    // --- RoPE on q, k (pairs r, r+64) ---
    if (tid < ROTD) {
        float c = cosb[b * ROTD + tid];
        float s = sinb[b * ROTD + tid];
        float q1 = qs[tid], q2 = qs[tid + ROTD];
        qs[tid] = q1 * c - q2 * s;
        qs[tid + ROTD] = q1 * s + q2 * c;
        float k1 = ks[tid], k2 = ks[tid + ROTD];
        ks[tid] = k1 * c - k2 * s;
        ks[tid + ROTD] = k1 * s + k2 * c;
    }
    __syncthreads();

    const float4 q4  = ((const float4*)qs)[lane];
    const float4 kn4 = ((const float4*)ks)[lane];

    const size_t rowstride = 2 * HEADS * DIM;
    const float* kbase = cache + (size_t)b * KVLEN * rowstride + h * DIM;

    // ---- pass 1: scores, 4 rows per warp-iter, pipelined loads ----
    {
        float4 k0 = __ldcs((const float4*)(kbase + (size_t)(warp)      * rowstride) + lane);
        float4 k1 = __ldcs((const float4*)(kbase + (size_t)(warp + 4)  * rowstride) + lane);
        float4 k2 = __ldcs((const float4*)(kbase + (size_t)(warp + 8)  * rowstride) + lane);
        float4 k3 = __ldcs((const float4*)(kbase + (size_t)(warp + 12) * rowstride) + lane);
        for (int s = warp; s < KVLEN; s += 16) {
            float4 n0, n1, n2, n3;
            int sn = s + 16;
            if (sn < KVLEN) {
                n0 = __ldcs((const float4*)(kbase + (size_t)sn        * rowstride) + lane);
                n1 = __ldcs((const float4*)(kbase + (size_t)(sn + 4)  * rowstride) + lane);
                n2 = __ldcs((const float4*)(kbase + (size_t)(sn + 8)  * rowstride) + lane);
                n3 = __ldcs((const float4*)(kbase + (size_t)(sn + 12) * rowstride) + lane);
            }
            if (s      == p) k0 = kn4;
            if (s + 4  == p) k1 = kn4;
            if (s + 8  == p) k2 = kn4;
            if (s + 12 == p) k3 = kn4;
            float d0 = q4.x*k0.x + q4.y*k0.y + q4.z*k0.z + q4.w*k0.w;
            float d1 = q4.x*k1.x + q4.y*k1.y + q4.z*k1.z + q4.w*k1.w;
            float d2 = q4.x*k2.x + q4.y*k2.y + q4.z*k2.z + q4.w*k2.w;
            float d3 = q4.x*k3.x + q4.y*k3.y + q4.z*k3.z + q4.w*k3.w;
#pragma unroll
            for (int o = 16; o > 0; o >>= 1) {
                d0 += __shfl_xor_sync(0xffffffffu, d0, o);
                d1 += __shfl_xor_sync(0xffffffffu, d1, o);
                d2 += __shfl_xor_sync(0xffffffffu, d2, o);
                d3 += __shfl_xor_sync(0xffffffffu, d3, o);
            }
            if (lane == 0) {
                sc[s]      = d0 * scale; sc[s + 4]  = d1 * scale;
                sc[s + 8]  = d2 * scale; sc[s + 12] = d3 * scale;
            }
            k0 = n0; k1 = n1; k2 = n2; k3 = n3;
        }
    }
    __syncthreads();

    // ---- softmax ----
    float m = -3.4e38f;
#pragma unroll
    for (int i = tid; i < KVLEN; i += 128) m = fmaxf(m, sc[i]);
#pragma unroll
    for (int o = 16; o > 0; o >>= 1)
        m = fmaxf(m, __shfl_xor_sync(0xffffffffu, m, o));
    if (lane == 0) wredA[warp] = m;
    __syncthreads();
    float bm = fmaxf(fmaxf(wredA[0], wredA[1]), fmaxf(wredA[2], wredA[3]));

    float ssum = 0.f;
#pragma unroll
    for (int i = tid; i < KVLEN; i += 128) {
        float e = __expf(sc[i] - bm);
        sc[i] = e;
        ssum += e;
    }
#pragma unroll
    for (int o = 16; o > 0; o >>= 1)
        ssum += __shfl_xor_sync(0xffffffffu, ssum, o);
    if (lane == 0) wredB[warp] = ssum;
    __syncthreads();
    const float inv = 1.0f / (wredB[0] + wredB[1] + wredB[2] + wredB[3]);

    // ---- pass 2: P @ V, 4 rows per warp-iter, pipelined loads ----
    const float* vbase = kbase + HEADS * DIM;
    const float4 vn4 = ((const float4*)vs)[lane];
    float4 acc = make_float4(0.f, 0.f, 0.f, 0.f);
    {
        float4 v0 = __ldcs((const float4*)(vbase + (size_t)(warp)      * rowstride) + lane);
        float4 v1 = __ldcs((const float4*)(vbase + (size_t)(warp + 4)  * rowstride) + lane);
        float4 v2 = __ldcs((const float4*)(vbase + (size_t)(warp + 8)  * rowstride) + lane);
        float4 v3 = __ldcs((const float4*)(vbase + (size_t)(warp + 12) * rowstride) + lane);
        for (int s = warp; s < KVLEN; s += 16) {
            float4 n0, n1, n2, n3;
            int sn = s + 16;
            if (sn < KVLEN) {
                n0 = __ldcs((const float4*)(vbase + (size_t)sn        * rowstride) + lane);
                n1 = __ldcs((const float4*)(vbase + (size_t)(sn + 4)  * rowstride) + lane);
                n2 = __ldcs((const float4*)(vbase + (size_t)(sn + 8)  * rowstride) + lane);
                n3 = __ldcs((const float4*)(vbase + (size_t)(sn + 12) * rowstride) + lane);
            }
            if (s      == p) v0 = vn4;
            if (s + 4  == p) v1 = vn4;
            if (s + 8  == p) v2 = vn4;
            if (s + 12 == p) v3 = vn4;
            float p0 = sc[s], p1 = sc[s + 4], p2 = sc[s + 8], p3 = sc[s + 12];
            acc.x += p0*v0.x + p1*v1.x + p2*v2.x + p3*v3.x;
            acc.y += p0*v0.y + p1*v1.y + p2*v2.y + p3*v3.y;
            acc.z += p0*v0.z + p1*v1.z + p2*v2.z + p3*v3.z;
            acc.w += p0*v0.w + p1*v1.w + p2*v2.w + p3*v3.w;
            v0 = n0; v1 = n1; v2 = n2; v3 = n3;
        }
    }
    ((float4*)(red + warp * DIM))[lane] = acc;
    __syncthreads();

    if (tid < DIM) {
        float o = red[tid] + red[DIM + tid] + red[2 * DIM + tid] + red[3 * DIM + tid];
        g_attn[(size_t)b * HID + h * DIM + tid] = o * inv;
    }
}

extern "C" void kernel_launch(void* const* d_in, const int* in_sizes, int n_in,
                              void* d_out, int out_size) {
    const float* hidden = (const float*)d_in[0];
    const float* cosb   = (const float*)d_in[1];
    const float* sinb   = (const float*)d_in[2];
    const float* cache  = (const float*)d_in[3];
    const int*   idx    = (const int*)d_in[4];
    const float* w_qkv  = (const float*)d_in[5];
    const float* w_o    = (const float*)d_in[6];
    float* out = (float*)d_out;

    float *attn_p, *part_p;
    cudaGetSymbolAddress((void**)&attn_p, g_attn);
    cudaGetSymbolAddress((void**)&part_p, g_part);

    // 1) QKV projection: 16 splits x chunk 256 (partials only; reduce fused into attn)
    gemm_splitk<256><<<dim3(NQKV / 256, QKV_SPLITS), 256>>>(hidden, w_qkv, part_p, NQKV, HID);
    // 2) attention: fused split-reduce + RoPE prologue, then KV streaming
    attn_kernel<<<BATCH * HEADS, 128>>>(part_p, cache, idx, cosb, sinb);
    // 3) output projection: 64 splits x chunk 64 + vectorized reduce
    gemm_splitk<64><<<dim3(HID / 256, OPJ_SPLITS), 256>>>(attn_p, w_o, part_p, HID, HID);
    reduce_splitk4<<<(BATCH * HID / 4 + 255) / 256, 256>>>(part_p, out, HID);
}